// round 3
// baseline (speedup 1.0000x reference)
#include <cuda_runtime.h>
#include <math.h>

#define BB 256   // batch
#define NS 32    // spans
#define DD 512   // feature dim

#define TR 8     // rows per block tile
#define TC 32    // cols per block tile
#define NQ 8     // K-split factor (64 k's per split)

// Scratch (allocation-free rule: __device__ globals)
__device__ float g_A[BB * DD];        // ner span-sums, [b][d], pre-scaled by 1/1024
__device__ float g_FT[DD * BB];       // face span-sums, TRANSPOSED [d][c]
__device__ float g_rowsum[BB];        // per-row sum(exp(logits))
__device__ float g_diagv[BB];         // logits[b][b]
__device__ unsigned int g_cnt;        // block arrival counter

// ---------------------------------------------------------------------------
// Kernel 1: span reductions. 512 blocks x 512 threads.
// Thread = (d4, span-group). 4 partial sums combined in shared memory.
// Also zeroes the kernel-2 accumulators (runs strictly before kernel 2).
// ---------------------------------------------------------------------------
__global__ void reduce_spans(const float* __restrict__ face,
                             const float* __restrict__ ner) {
    const int blk = blockIdx.x;
    const int tid = threadIdx.x;
    const int t4  = tid & 127;     // float4 index within row (128 * 4 = 512 d)
    const int grp = tid >> 7;      // span group 0..3 (8 spans each)

    if (blk == 0) {
        if (tid < BB) g_rowsum[tid] = 0.f;
        if (tid == BB) g_cnt = 0u;
    }

    const bool is_ner = (blk < BB);
    const int row = is_ner ? blk : blk - BB;
    const float4* src = reinterpret_cast<const float4*>(
        (is_ner ? ner : face) + (size_t)row * NS * DD);

    float4 s = make_float4(0.f, 0.f, 0.f, 0.f);
#pragma unroll
    for (int n = 0; n < 8; n++) {
        float4 v = src[(grp * 8 + n) * (DD / 4) + t4];
        s.x += v.x; s.y += v.y; s.z += v.z; s.w += v.w;
    }

    __shared__ float4 sp[3][128];
    if (grp > 0) sp[grp - 1][t4] = s;
    __syncthreads();

    if (grp == 0) {
#pragma unroll
        for (int i = 0; i < 3; i++) {
            float4 v = sp[i][t4];
            s.x += v.x; s.y += v.y; s.z += v.z; s.w += v.w;
        }
        if (is_ner) {
            const float inv = 1.0f / 1024.0f;   // fold the 1/(N1*N2) mean
            s.x *= inv; s.y *= inv; s.z *= inv; s.w *= inv;
            reinterpret_cast<float4*>(g_A + row * DD)[t4] = s;
        } else {
            const int d = t4 * 4;
            g_FT[(d + 0) * BB + row] = s.x;
            g_FT[(d + 1) * BB + row] = s.y;
            g_FT[(d + 2) * BB + row] = s.z;
            g_FT[(d + 3) * BB + row] = s.w;
        }
    }
}

// ---------------------------------------------------------------------------
// Kernel 2: tiled GEMM (8 rows x 32 cols per block) + fused no-max softmax
// row-sums via atomics + last-block finalize.
// grid = 256 blocks, 256 threads. Thread = (cl = tid&31, q = tid>>5).
// Inner loop: 1 coalesced LDG (FT col) + 2 broadcast LDS.128 (A rows) + 8 FMA.
// ---------------------------------------------------------------------------
__global__ void gemm_lse(float* __restrict__ out) {
    const int bx = blockIdx.x;
    const int row_tile = bx >> 3;        // 0..31
    const int col_tile = bx & 7;         // 0..7
    const int r0 = row_tile * TR;
    const int c0 = col_tile * TC;
    const int tid = threadIdx.x;
    const int cl  = tid & 31;            // local col
    const int q   = tid >> 5;            // k-split 0..7
    const int c   = c0 + cl;             // global col

    // A tile, transposed: sAT[k][r]
    __shared__ float sAT[DD * TR];       // 16 KB
    for (int i = tid; i < DD * TR; i += 256) {
        const int k = i >> 3;
        const int r = i & 7;
        sAT[i] = g_A[(r0 + r) * DD + k];
    }
    __syncthreads();

    float acc[TR];
#pragma unroll
    for (int r = 0; r < TR; r++) acc[r] = 0.f;

    const int kbase = q * (DD / NQ);     // 64 k's per split
#pragma unroll 8
    for (int kk = 0; kk < DD / NQ; kk++) {
        const int k = kbase + kk;
        const float f = g_FT[k * BB + c];
        const float4 a0 = *reinterpret_cast<const float4*>(sAT + k * TR);
        const float4 a1 = *reinterpret_cast<const float4*>(sAT + k * TR + 4);
        acc[0] = fmaf(a0.x, f, acc[0]);
        acc[1] = fmaf(a0.y, f, acc[1]);
        acc[2] = fmaf(a0.z, f, acc[2]);
        acc[3] = fmaf(a0.w, f, acc[3]);
        acc[4] = fmaf(a1.x, f, acc[4]);
        acc[5] = fmaf(a1.y, f, acc[5]);
        acc[6] = fmaf(a1.z, f, acc[6]);
        acc[7] = fmaf(a1.w, f, acc[7]);
    }

    // combine k-splits: sP[q][cl][r] (padded to kill bank conflicts)
    __shared__ float sP[NQ][TC][TR + 1]; // ~9.2 KB
#pragma unroll
    for (int r = 0; r < TR; r++) sP[q][cl][r] = acc[r];
    __syncthreads();

    // thread (cl2, r2) owns logits[r0+r2][c0+cl2]
    const int cl2 = tid & 31;
    const int r2  = tid >> 5;
    float l = 0.f;
#pragma unroll
    for (int qq = 0; qq < NQ; qq++) l += sP[qq][cl2][r2];

    if (c0 + cl2 == r0 + r2) g_diagv[r0 + r2] = l;

    // per-row partial sum(exp) over this block's 32 cols: one warp per row
    float e = __expf(l);
#pragma unroll
    for (int o = 16; o; o >>= 1) e += __shfl_xor_sync(0xffffffffu, e, o);
    if (cl2 == 0) atomicAdd(&g_rowsum[r0 + r2], e);

    // ---- last-arriving block finalizes ----
    __shared__ unsigned int arrival;
    __syncthreads();                     // all atomics of this block issued
    if (tid == 0) {
        __threadfence();
        arrival = atomicAdd(&g_cnt, 1u);
    }
    __syncthreads();

    if (arrival == 255u) {
        __threadfence();
        volatile float* vs = g_rowsum;
        volatile float* vd = g_diagv;
        float v = vd[tid] - logf(vs[tid]);   // logp[b][b]
        const int lane = tid & 31;
        const int warp = tid >> 5;
        __shared__ float red[8];
#pragma unroll
        for (int o = 16; o; o >>= 1) v += __shfl_xor_sync(0xffffffffu, v, o);
        if (lane == 0) red[warp] = v;
        __syncthreads();
        if (tid == 0) {
            float s = red[0];
#pragma unroll
            for (int i = 1; i < 8; i++) s += red[i];
            out[0] = -s * (1.0f / 256.0f);
        }
    }
}

extern "C" void kernel_launch(void* const* d_in, const int* in_sizes, int n_in,
                              void* d_out, int out_size) {
    const float* face = (const float*)d_in[0];  // (256, 32, 512)
    const float* ner  = (const float*)d_in[1];  // (256, 32, 512)
    float* out = (float*)d_out;

    reduce_spans<<<2 * BB, 512>>>(face, ner);
    gemm_lse<<<BB, 256>>>(out);
}

// round 4
// speedup vs baseline: 1.4810x; 1.4810x over previous
#include <cuda_runtime.h>
#include <math.h>

#define BB 256   // batch
#define NS 32    // spans
#define DD 512   // feature dim

#define TR 4     // rows per block tile
#define TC 32    // cols per block tile
#define NQ 8     // K-split factor within block (64 k's per split)

// Scratch (allocation-free rule: __device__ globals)
__device__ float g_A[BB * DD];        // ner span-sums, [b][d], pre-scaled by 1/1024
__device__ float g_FT[DD * BB];       // face span-sums, TRANSPOSED [d][c]
__device__ float g_rowsum[BB];        // per-row sum(exp(logits))
__device__ float g_diagv[BB];         // logits[b][b]
__device__ unsigned int g_cnt;        // block arrival counter

// ---------------------------------------------------------------------------
// Kernel 1: span reductions. 512 blocks x 512 threads.
// Thread = (d4, span-group). 4 partial sums combined in shared memory.
// Also zeroes the kernel-2 accumulators (runs strictly before kernel 2).
// ---------------------------------------------------------------------------
__global__ void reduce_spans(const float* __restrict__ face,
                             const float* __restrict__ ner) {
    const int blk = blockIdx.x;
    const int tid = threadIdx.x;
    const int t4  = tid & 127;     // float4 index within row (128 * 4 = 512 d)
    const int grp = tid >> 7;      // span group 0..3 (8 spans each)

    if (blk == 0) {
        if (tid < BB) g_rowsum[tid] = 0.f;
        if (tid == BB) g_cnt = 0u;
    }

    const bool is_ner = (blk < BB);
    const int row = is_ner ? blk : blk - BB;
    const float4* src = reinterpret_cast<const float4*>(
        (is_ner ? ner : face) + (size_t)row * NS * DD);

    float4 s = make_float4(0.f, 0.f, 0.f, 0.f);
#pragma unroll
    for (int n = 0; n < 8; n++) {
        float4 v = src[(grp * 8 + n) * (DD / 4) + t4];
        s.x += v.x; s.y += v.y; s.z += v.z; s.w += v.w;
    }

    __shared__ float4 sp[3][128];
    if (grp > 0) sp[grp - 1][t4] = s;
    __syncthreads();

    if (grp == 0) {
#pragma unroll
        for (int i = 0; i < 3; i++) {
            float4 v = sp[i][t4];
            s.x += v.x; s.y += v.y; s.z += v.z; s.w += v.w;
        }
        if (is_ner) {
            const float inv = 1.0f / 1024.0f;   // fold the 1/(N1*N2) mean
            s.x *= inv; s.y *= inv; s.z *= inv; s.w *= inv;
            reinterpret_cast<float4*>(g_A + row * DD)[t4] = s;
        } else {
            const int d = t4 * 4;
            g_FT[(d + 0) * BB + row] = s.x;
            g_FT[(d + 1) * BB + row] = s.y;
            g_FT[(d + 2) * BB + row] = s.z;
            g_FT[(d + 3) * BB + row] = s.w;
        }
    }
}

// ---------------------------------------------------------------------------
// Kernel 2: tiled GEMM (4 rows x 32 cols per block, k-split 8) + fused
// no-max softmax row-sums via atomics + last-block finalize.
// grid = 512 blocks x 256 threads (131K threads, ~3.5 blocks/SM).
// Thread = (cl = tid&31, q = tid>>5). Inner loop:
//   1 coalesced LDG (FT col) + 1 broadcast LDS.128 (4 A rows) + 4 FMA.
// ---------------------------------------------------------------------------
__global__ void gemm_lse(float* __restrict__ out) {
    const int bx = blockIdx.x;
    const int row_tile = bx >> 3;        // 0..63
    const int col_tile = bx & 7;         // 0..7
    const int r0 = row_tile * TR;
    const int c0 = col_tile * TC;
    const int tid = threadIdx.x;
    const int cl  = tid & 31;            // local col
    const int q   = tid >> 5;            // k-split 0..7
    const int c   = c0 + cl;             // global col

    // A tile, transposed: sAT[k][r] (k-major, 4 rows contiguous -> LDS.128)
    __shared__ float sAT[DD * TR];       // 8 KB
    // Coalesced fill: thread walks k (float4 of 4 consecutive k) per row.
    {
#pragma unroll
        for (int j = 0; j < 2; j++) {
            const int idx = j * 256 + tid;        // 0..511 float4 slots
            const int r   = idx >> 7;             // 0..3
            const int k4  = idx & 127;            // float4 index along k
            const float4 v = reinterpret_cast<const float4*>(
                g_A + (r0 + r) * DD)[k4];
            sAT[(k4 * 4 + 0) * TR + r] = v.x;
            sAT[(k4 * 4 + 1) * TR + r] = v.y;
            sAT[(k4 * 4 + 2) * TR + r] = v.z;
            sAT[(k4 * 4 + 3) * TR + r] = v.w;
        }
    }
    __syncthreads();

    float acc0 = 0.f, acc1 = 0.f, acc2 = 0.f, acc3 = 0.f;
    const int kbase = q * (DD / NQ);     // 64 k's per split
#pragma unroll 8
    for (int kk = 0; kk < DD / NQ; kk++) {
        const int k = kbase + kk;
        const float f = g_FT[k * BB + c];                  // coalesced LDG
        const float4 a = *reinterpret_cast<const float4*>(sAT + k * TR); // broadcast
        acc0 = fmaf(a.x, f, acc0);
        acc1 = fmaf(a.y, f, acc1);
        acc2 = fmaf(a.z, f, acc2);
        acc3 = fmaf(a.w, f, acc3);
    }

    // combine k-splits: sP[q][cl][r] (padded against bank conflicts)
    __shared__ float sP[NQ][TC][TR + 1]; // 5 KB
    sP[q][cl][0] = acc0;
    sP[q][cl][1] = acc1;
    sP[q][cl][2] = acc2;
    sP[q][cl][3] = acc3;
    __syncthreads();

    // threads 0..127: thread (cl2, r2) owns logits[r0+r2][c0+cl2]
    if (tid < TC * TR) {
        const int cl2 = tid & 31;
        const int r2  = tid >> 5;        // 0..3
        float l = 0.f;
#pragma unroll
        for (int qq = 0; qq < NQ; qq++) l += sP[qq][cl2][r2];

        if (c0 + cl2 == r0 + r2) g_diagv[r0 + r2] = l;

        // per-row partial sum(exp) over this block's 32 cols: one warp per row
        float e = __expf(l);
#pragma unroll
        for (int o = 16; o; o >>= 1) e += __shfl_xor_sync(0xffffffffu, e, o);
        if (cl2 == 0) atomicAdd(&g_rowsum[r0 + r2], e);
    }

    // ---- last-arriving block finalizes ----
    __shared__ unsigned int arrival;
    __syncthreads();                     // all atomics of this block issued
    if (tid == 0) {
        __threadfence();
        arrival = atomicAdd(&g_cnt, 1u);
    }
    __syncthreads();

    if (arrival == (unsigned int)(8 * (BB / TR) - 1)) {   // 511
        __threadfence();
        volatile float* vs = g_rowsum;
        volatile float* vd = g_diagv;
        float v = vd[tid] - logf(vs[tid]);   // logp[b][b]
        const int lane = tid & 31;
        const int warp = tid >> 5;
        __shared__ float red[8];
#pragma unroll
        for (int o = 16; o; o >>= 1) v += __shfl_xor_sync(0xffffffffu, v, o);
        if (lane == 0) red[warp] = v;
        __syncthreads();
        if (tid == 0) {
            float s = red[0];
#pragma unroll
            for (int i = 1; i < 8; i++) s += red[i];
            out[0] = -s * (1.0f / 256.0f);
        }
    }
}

extern "C" void kernel_launch(void* const* d_in, const int* in_sizes, int n_in,
                              void* d_out, int out_size) {
    const float* face = (const float*)d_in[0];  // (256, 32, 512)
    const float* ner  = (const float*)d_in[1];  // (256, 32, 512)
    float* out = (float*)d_out;

    reduce_spans<<<2 * BB, 512>>>(face, ner);
    gemm_lse<<<8 * (BB / TR), 256>>>(out);
}

// round 5
// speedup vs baseline: 1.5970x; 1.0784x over previous
#include <cuda_runtime.h>
#include <math.h>

#define BB 256   // batch
#define NS 32    // spans
#define DD 512   // feature dim

#define TR 2     // rows per block tile
#define TC 64    // cols per block tile (16 threads x 4 cols via float4)
#define NQ 16    // K-split factor within block (32 k's per split)

// Scratch (allocation-free rule: __device__ globals)
__device__ float g_A[BB * DD];        // ner span-sums, [b][d], pre-scaled by 1/1024
__device__ float g_FT[DD * BB];       // face span-sums, TRANSPOSED [d][c]
__device__ float g_rowsum[BB];        // per-row sum(exp(logits))
__device__ float g_diagv[BB];         // logits[b][b]
__device__ unsigned int g_cnt;        // block arrival counter

// ---------------------------------------------------------------------------
// Kernel 1: span reductions. 512 blocks x 512 threads.
// Thread = (d4, span-group). 4 partial sums combined in shared memory.
// Also zeroes the kernel-2 accumulators (runs strictly before kernel 2).
// ---------------------------------------------------------------------------
__global__ void reduce_spans(const float* __restrict__ face,
                             const float* __restrict__ ner) {
    const int blk = blockIdx.x;
    const int tid = threadIdx.x;
    const int t4  = tid & 127;     // float4 index within row (128 * 4 = 512 d)
    const int grp = tid >> 7;      // span group 0..3 (8 spans each)

    if (blk == 0) {
        if (tid < BB) g_rowsum[tid] = 0.f;
        if (tid == BB) g_cnt = 0u;
    }

    const bool is_ner = (blk < BB);
    const int row = is_ner ? blk : blk - BB;
    const float4* src = reinterpret_cast<const float4*>(
        (is_ner ? ner : face) + (size_t)row * NS * DD);

    float4 s = make_float4(0.f, 0.f, 0.f, 0.f);
#pragma unroll
    for (int n = 0; n < 8; n++) {
        float4 v = src[(grp * 8 + n) * (DD / 4) + t4];
        s.x += v.x; s.y += v.y; s.z += v.z; s.w += v.w;
    }

    __shared__ float4 sp[3][128];
    if (grp > 0) sp[grp - 1][t4] = s;
    __syncthreads();

    if (grp == 0) {
#pragma unroll
        for (int i = 0; i < 3; i++) {
            float4 v = sp[i][t4];
            s.x += v.x; s.y += v.y; s.z += v.z; s.w += v.w;
        }
        if (is_ner) {
            const float inv = 1.0f / 1024.0f;   // fold the 1/(N1*N2) mean
            s.x *= inv; s.y *= inv; s.z *= inv; s.w *= inv;
            reinterpret_cast<float4*>(g_A + row * DD)[t4] = s;
        } else {
            const int d = t4 * 4;
            g_FT[(d + 0) * BB + row] = s.x;
            g_FT[(d + 1) * BB + row] = s.y;
            g_FT[(d + 2) * BB + row] = s.z;
            g_FT[(d + 3) * BB + row] = s.w;
        }
    }
}

// ---------------------------------------------------------------------------
// Kernel 2: tiled GEMM (2 rows x 64 cols per block, k-split 16) + fused
// no-max softmax row-sums via atomics + last-block finalize.
// grid = 512 blocks x 256 threads. Thread = (cl = tid&15 -> 4 cols via
// float4, q = tid>>4 -> 32 k's). Inner loop:
//   1 LDG.128 (FT, 4 cols) + 1 broadcast LDS.64 (2 A rows) + 8 FMA.
// ---------------------------------------------------------------------------
__global__ void gemm_lse(float* __restrict__ out) {
    const int bx = blockIdx.x;
    const int row_tile = bx >> 2;        // 0..127
    const int col_tile = bx & 3;         // 0..3
    const int r0 = row_tile * TR;
    const int c0 = col_tile * TC;
    const int tid = threadIdx.x;
    const int cl  = tid & 15;            // col group (4 cols)
    const int q   = tid >> 4;            // k-split 0..15
    const int c   = c0 + cl * 4;         // first of 4 global cols

    // A tile, transposed: sAT[k][r] (k-major, 2 rows contiguous -> LDS.64)
    __shared__ float sAT[DD * TR];       // 4 KB
    // Coalesced fill: 256 float4 slots, one per thread.
    {
        const int r  = tid >> 7;          // 0..1
        const int k4 = tid & 127;         // float4 index along k
        const float4 v = reinterpret_cast<const float4*>(
            g_A + (r0 + r) * DD)[k4];
        sAT[(k4 * 4 + 0) * TR + r] = v.x;
        sAT[(k4 * 4 + 1) * TR + r] = v.y;
        sAT[(k4 * 4 + 2) * TR + r] = v.z;
        sAT[(k4 * 4 + 3) * TR + r] = v.w;
    }
    __syncthreads();

    float acc[TR][4];
#pragma unroll
    for (int r = 0; r < TR; r++)
#pragma unroll
        for (int j = 0; j < 4; j++) acc[r][j] = 0.f;

    const int kbase = q * (DD / NQ);     // 32 k's per split
#pragma unroll 8
    for (int kk = 0; kk < DD / NQ; kk++) {
        const int k = kbase + kk;
        const float4 f = *reinterpret_cast<const float4*>(g_FT + k * BB + c);
        const float2 a = *reinterpret_cast<const float2*>(sAT + k * TR);
        acc[0][0] = fmaf(a.x, f.x, acc[0][0]);
        acc[0][1] = fmaf(a.x, f.y, acc[0][1]);
        acc[0][2] = fmaf(a.x, f.z, acc[0][2]);
        acc[0][3] = fmaf(a.x, f.w, acc[0][3]);
        acc[1][0] = fmaf(a.y, f.x, acc[1][0]);
        acc[1][1] = fmaf(a.y, f.y, acc[1][1]);
        acc[1][2] = fmaf(a.y, f.z, acc[1][2]);
        acc[1][3] = fmaf(a.y, f.w, acc[1][3]);
    }

    // combine k-splits: sP[q][cl][8 accs + pad]
    __shared__ float sP[NQ][16][TR * 4 + 1];   // ~9.2 KB
#pragma unroll
    for (int r = 0; r < TR; r++)
#pragma unroll
        for (int j = 0; j < 4; j++) sP[q][cl][r * 4 + j] = acc[r][j];
    __syncthreads();

    // threads 0..127: thread owns logits[r0+r2][c0+c2l]
    if (tid < TR * TC) {                 // 128
        const int r2  = tid >> 6;        // 0..1
        const int c2l = tid & 63;        // 0..63
        const int clo = c2l >> 2;
        const int jj  = c2l & 3;
        float l = 0.f;
#pragma unroll
        for (int qq = 0; qq < NQ; qq++) l += sP[qq][clo][r2 * 4 + jj];

        if (c0 + c2l == r0 + r2) g_diagv[r0 + r2] = l;

        // per-row partial sum(exp): 2 warps per row, warp-reduce + atomic
        float e = __expf(l);
#pragma unroll
        for (int o = 16; o; o >>= 1) e += __shfl_xor_sync(0xffffffffu, e, o);
        if ((tid & 31) == 0) atomicAdd(&g_rowsum[r0 + r2], e);
    }

    // ---- last-arriving block finalizes ----
    __shared__ unsigned int arrival;
    __syncthreads();                     // all atomics of this block issued
    if (tid == 0) {
        __threadfence();
        arrival = atomicAdd(&g_cnt, 1u);
    }
    __syncthreads();

    if (arrival == 511u) {
        __threadfence();
        volatile float* vs = g_rowsum;
        volatile float* vd = g_diagv;
        float v = vd[tid] - logf(vs[tid]);   // logp[b][b]
        const int lane = tid & 31;
        const int warp = tid >> 5;
        __shared__ float red[8];
#pragma unroll
        for (int o = 16; o; o >>= 1) v += __shfl_xor_sync(0xffffffffu, v, o);
        if (lane == 0) red[warp] = v;
        __syncthreads();
        if (tid == 0) {
            float s = red[0];
#pragma unroll
            for (int i = 1; i < 8; i++) s += red[i];
            out[0] = -s * (1.0f / 256.0f);
        }
    }
}

extern "C" void kernel_launch(void* const* d_in, const int* in_sizes, int n_in,
                              void* d_out, int out_size) {
    const float* face = (const float*)d_in[0];  // (256, 32, 512)
    const float* ner  = (const float*)d_in[1];  // (256, 32, 512)
    float* out = (float*)d_out;

    reduce_spans<<<2 * BB, 512>>>(face, ner);
    gemm_lse<<<512, 256>>>(out);
}